// round 3
// baseline (speedup 1.0000x reference)
#include <cuda_runtime.h>
#include <math.h>

// Problem constants (fixed by the dataset instance)
#define TQ    2000          // max_query (T_OUT)
#define KIN   400           // max_key (T_IN)
#define SMAX  (2 * KIN + 1) // 801 CTC extended states
#define NEGF  (-1e30f)
#define BLANKF (-1.0f)
#define MAXB  128

// Scratch (allocation-free rule: __device__ globals)
__device__ float g_lse[MAXB * TQ];   // log-sum-exp denominator per (b, t)
__device__ float g_losses[MAXB];     // per-batch loss

// ---------------------------------------------------------------------------
// Kernel 1: per-row log-softmax denominator.
// LSE[b][t] = log( exp(BLANK) + sum_{k < in_len[b]} exp(attn[b,t,k]) )
// One warp per row; fully parallel, HBM-bound.
// ---------------------------------------------------------------------------
__global__ void lse_kernel(const float* __restrict__ attn,
                           const int* __restrict__ in_lens, int B) {
    const int warps = blockDim.x >> 5;
    const int row = blockIdx.x * warps + (threadIdx.x >> 5);
    if (row >= B * TQ) return;
    const int b = row / TQ;
    const int L = in_lens[b];
    const float* p = attn + (size_t)row * KIN;
    const int lane = threadIdx.x & 31;
    float s = 0.f;
    for (int k = lane; k < L; k += 32) s += __expf(__ldg(p + k));
    #pragma unroll
    for (int o = 16; o; o >>= 1) s += __shfl_xor_sync(0xffffffffu, s, o);
    if (lane == 0) g_lse[row] = __logf(s + __expf(BLANKF));
}

// ---------------------------------------------------------------------------
// Kernel 2: CTC forward recursion, one CTA per batch element.
// alpha double-buffered in SMEM with a 2-element NEG halo so alpha[s-1],
// alpha[s-2] need no branches. One __syncthreads per time step.
// Per-thread register prefetch of next row's attn values hides DRAM latency.
// ---------------------------------------------------------------------------
__global__ __launch_bounds__(256, 1)
void ctc_kernel(const float* __restrict__ attn,
                const int* __restrict__ in_lens,
                const int* __restrict__ out_lens) {
    __shared__ float bufA[SMAX + 2];
    __shared__ float bufB[SMAX + 2];

    const int b   = blockIdx.x;
    const int tid = threadIdx.x;
    const int L   = in_lens[b];
    const int OL  = out_lens[b];
    const int last = 2 * L;

    for (int i = tid; i < SMAX + 2; i += 256) { bufA[i] = NEGF; bufB[i] = NEGF; }
    float* cur = bufA;
    float* nxt = bufB;

    const float* rowbase = attn + (size_t)b * TQ * KIN;
    const float* lsebase = g_lse + b * TQ;
    __syncthreads();

    // t = 0 init: alpha[0] = em(0, blank), alpha[1] = em(0, token 1)
    if (tid == 0) {
        float lse0 = lsebase[0];
        cur[2 + 0] = BLANKF - lse0;
        cur[2 + 1] = __ldg(rowbase + 0) - lse0;  // tok=1 always valid (L >= 200)
    }
    __syncthreads();

    // Per-thread state metadata (states s = tid + 256*j)
    int  sj[4];  int tk[4];  bool odd[4];  bool val[4];
    #pragma unroll
    for (int j = 0; j < 4; j++) {
        int s = tid + j * 256;
        sj[j]  = s;
        odd[j] = (s & 1) != 0;
        int tok = (s + 1) >> 1;
        tk[j]  = tok - 1;
        val[j] = odd[j] && (tok <= L) && (s < SMAX);
    }

    // Prefetch row values for t = 1
    float rvn[4];
    #pragma unroll
    for (int j = 0; j < 4; j++) rvn[j] = NEGF;
    #pragma unroll
    for (int j = 0; j < 4; j++)
        if (val[j]) rvn[j] = __ldg(rowbase + (size_t)KIN + tk[j]);

    for (int t = 1; t < OL; t++) {
        const float lse = __ldg(lsebase + t);
        float rv[4];
        #pragma unroll
        for (int j = 0; j < 4; j++) rv[j] = rvn[j];

        // Prefetch next row (clamped; redundant last fetch is harmless)
        const int tn = (t + 1 < OL) ? (t + 1) : (OL - 1);
        #pragma unroll
        for (int j = 0; j < 4; j++)
            if (val[j]) rvn[j] = __ldg(rowbase + (size_t)tn * KIN + tk[j]);

        const int hi = 2 * t + 1;                     // forward reachability
        const int lo = (last - 1) - 2 * (OL - 1 - t); // backward reachability
        const float emB = BLANKF - lse;

        #pragma unroll
        for (int j = 0; j < 4; j++) {
            const int s = sj[j];
            if (s >= SMAX || s > hi) break;  // sj increasing in j
            if (s < lo) continue;            // stale slots are never read
            const float a  = cur[s + 2];
            const float a1 = cur[s + 1];
            const float a2 = (odd[j] && s >= 3) ? cur[s] : NEGF;
            const float m  = fmaxf(fmaxf(a, a1), a2);
            const float sum = __expf(a - m) + __expf(a1 - m) + __expf(a2 - m);
            const float em = odd[j] ? (val[j] ? rv[j] - lse : NEGF) : emB;
            nxt[s + 2] = m + __logf(sum) + em;
        }
        __syncthreads();
        float* tmp = cur; cur = nxt; nxt = tmp;
    }

    if (tid == 0) {
        const float aS   = cur[2 + last];
        const float aSm1 = cur[2 + last - 1];
        const float m  = fmaxf(aS, aSm1);
        const float ll = m + __logf(__expf(aS - m) + __expf(aSm1 - m));
        float loss = -ll / (float)L;
        if (!isfinite(loss) || !(ll > NEGF * 0.5f)) loss = 0.f;
        g_losses[b] = loss;
    }
}

// ---------------------------------------------------------------------------
// Kernel 3: mean over batch -> scalar output
// ---------------------------------------------------------------------------
__global__ void reduce_kernel(float* __restrict__ out, int B) {
    float s = 0.f;
    for (int i = threadIdx.x; i < B; i += 32) s += g_losses[i];
    #pragma unroll
    for (int o = 16; o; o >>= 1) s += __shfl_xor_sync(0xffffffffu, s, o);
    if (threadIdx.x == 0) out[0] = s / (float)B;
}

extern "C" void kernel_launch(void* const* d_in, const int* in_sizes, int n_in,
                              void* d_out, int out_size) {
    const float* attn     = (const float*)d_in[0];
    const int*   in_lens  = (const int*)d_in[1];
    const int*   out_lens = (const int*)d_in[2];
    int B = in_sizes[1];
    if (B > MAXB) B = MAXB;

    const int rows = B * TQ;
    const int warps_per_block = 8;
    lse_kernel<<<(rows + warps_per_block - 1) / warps_per_block,
                 warps_per_block * 32>>>(attn, in_lens, B);
    ctc_kernel<<<B, 256>>>(attn, in_lens, out_lens);
    reduce_kernel<<<1, 32>>>((float*)d_out, B);
}

// round 4
// speedup vs baseline: 1.9930x; 1.9930x over previous
#include <cuda_runtime.h>
#include <math.h>

#define TQ    2000
#define KIN   400
#define SMAX  801            // 2*KIN+1 states
#define MAXB  128
#define LOG2E 1.4426950408889634f
#define LN2   0.6931471805599453f
#define ANEG  (-1e7f)        // "minus infinity" in log2 domain (safe: exp2->0, no inf/NaN)
#define NEGEM (-1e7f)

__device__ float g_lse[MAXB * TQ];   // log2( sum_k e^{x_k} + e^{-1} ) per (b,t)
__device__ float g_losses[MAXB];

__device__ __forceinline__ float ex2(float x) {
    float r; asm("ex2.approx.ftz.f32 %0, %1;" : "=f"(r) : "f"(x)); return r;
}
__device__ __forceinline__ float lg2(float x) {
    float r; asm("lg2.approx.ftz.f32 %0, %1;" : "=f"(r) : "f"(x)); return r;
}

// ---------------------------------------------------------------------------
// Kernel 1: per-row log-softmax denominator (log2 domain), float4 vectorized.
// One warp per row; skips rows beyond out_len (never read by ctc kernel).
// ---------------------------------------------------------------------------
__global__ void lse_kernel(const float* __restrict__ attn,
                           const int* __restrict__ in_lens,
                           const int* __restrict__ out_lens, int B) {
    const int warps = blockDim.x >> 5;
    const int row = blockIdx.x * warps + (threadIdx.x >> 5);
    if (row >= B * TQ) return;
    const int b = row / TQ;
    const int t = row - b * TQ;
    if (t >= out_lens[b]) return;
    const int L = in_lens[b];
    const float* p = attn + (size_t)row * KIN;
    const float4* p4 = (const float4*)p;
    const int lane = threadIdx.x & 31;
    float s = 0.f;
    const int L4 = L >> 2;
    for (int k = lane; k < L4; k += 32) {
        float4 v = __ldg(p4 + k);
        s += ex2(v.x * LOG2E) + ex2(v.y * LOG2E)
           + ex2(v.z * LOG2E) + ex2(v.w * LOG2E);
    }
    const int rem = L & 3;
    if (lane < rem) s += ex2(__ldg(p + L4 * 4 + lane) * LOG2E);
    #pragma unroll
    for (int o = 16; o; o >>= 1) s += __shfl_xor_sync(0xffffffffu, s, o);
    if (lane == 0) g_lse[row] = lg2(s + 0.36787944117144233f);  // + e^{-1}
}

// ---------------------------------------------------------------------------
// Kernel 2: CTC forward recursion. One CTA per batch, 832 threads, 1 state
// per thread. Warps 0-12 (tid<416): even (blank) states s=2i, i=tid.
// Warps 13-25: odd (token) states s=2i+1, i=tid-416.
// Alpha stored de-interleaved: E[i+1]=alpha[2i], O[i+1]=alpha[2i+1],
// index 0 is a NEG halo. All smem accesses stride-1, conflict-free.
// One __syncthreads per step (double buffered). Everything log2-domain.
// ---------------------------------------------------------------------------
__global__ __launch_bounds__(832, 1)
void ctc_kernel(const float* __restrict__ attn,
                const int* __restrict__ in_lens,
                const int* __restrict__ out_lens) {
    __shared__ float bufE[2][417];
    __shared__ float bufO[2][417];

    const int b   = blockIdx.x;
    const int tid = threadIdx.x;
    const int L   = in_lens[b];
    const int OL  = out_lens[b];

    const bool isOdd = (tid >= 416);
    const int  i     = isOdd ? tid - 416 : tid;

    for (int k = tid; k < 417; k += 832) {
        bufE[0][k] = ANEG; bufE[1][k] = ANEG;
        bufO[0][k] = ANEG; bufO[1][k] = ANEG;
    }

    const float* rowbase = attn + (size_t)b * TQ * KIN;
    const float* lsebase = g_lse + b * TQ;
    __syncthreads();

    if (tid == 0) {
        const float l0 = lsebase[0];
        bufE[0][1] = -LOG2E - l0;                 // state 0: blank emission
        bufO[0][1] = rowbase[0] * LOG2E - l0;     // state 1: token 1
    }
    __syncthreads();

    const bool tokValid = isOdd && (i < L);       // token i+1 <= L, i < 400
    const bool evReal   = !isOdd && (i <= 400);

    // Distance-2 prefetch pipeline for attn row values and lse
    float rv1 = tokValid ? __ldg(rowbase + KIN + i) : 0.f;
    float ls1 = __ldg(lsebase + 1);
    const int t2i = (OL > 2) ? 2 : OL - 1;
    float rv2 = tokValid ? __ldg(rowbase + (size_t)t2i * KIN + i) : 0.f;
    float ls2 = __ldg(lsebase + t2i);

    int cb = 0;
    for (int t = 1; t < OL; t++) {
        const float lsev = ls1;
        const float rvv  = rv1;
        rv1 = rv2; ls1 = ls2;
        const int tn = (t + 2 < OL) ? (t + 2) : (OL - 1);
        rv2 = tokValid ? __ldg(rowbase + (size_t)tn * KIN + i) : 0.f;
        ls2 = __ldg(lsebase + tn);

        float newv;
        if (isOdd) {                               // token state (warp-uniform)
            const float em2 = tokValid ? fmaf(rvv, LOG2E, -lsev) : NEGEM;
            const float a  = bufO[cb][i + 1];
            const float a1 = bufE[cb][i + 1];
            const float a2 = bufO[cb][i];
            const float m  = fmaxf(fmaxf(a, a1), a2);
            const float s  = ex2(a - m) + ex2(a1 - m) + ex2(a2 - m);
            newv = m + lg2(s) + em2;
            bufO[cb ^ 1][i + 1] = newv;
        } else {                                   // blank state
            const float em2 = evReal ? (-LOG2E - lsev) : 0.f;
            const float a  = bufE[cb][i + 1];
            const float a1 = bufO[cb][i];
            const float m  = fmaxf(a, a1);
            const float s  = ex2(a - m) + ex2(a1 - m);
            newv = m + lg2(s) + em2;
            bufE[cb ^ 1][i + 1] = newv;
        }
        __syncthreads();
        cb ^= 1;
    }

    if (tid == 0) {
        const float aS   = bufE[cb][L + 1];        // state 2L   (even idx L)
        const float aSm1 = bufO[cb][L];            // state 2L-1 (odd idx L-1)
        const float m    = fmaxf(aS, aSm1);
        const float ll2  = m + lg2(ex2(aS - m) + ex2(aSm1 - m));
        const float ll   = ll2 * LN2;
        float loss = -ll / (float)L;
        if (!(ll > -1e6f) || !isfinite(loss)) loss = 0.f;
        g_losses[b] = loss;
    }
}

// ---------------------------------------------------------------------------
// Kernel 3: mean over batch -> scalar
// ---------------------------------------------------------------------------
__global__ void reduce_kernel(float* __restrict__ out, int B) {
    float s = 0.f;
    for (int k = threadIdx.x; k < B; k += 32) s += g_losses[k];
    #pragma unroll
    for (int o = 16; o; o >>= 1) s += __shfl_xor_sync(0xffffffffu, s, o);
    if (threadIdx.x == 0) out[0] = s / (float)B;
}

extern "C" void kernel_launch(void* const* d_in, const int* in_sizes, int n_in,
                              void* d_out, int out_size) {
    const float* attn     = (const float*)d_in[0];
    const int*   in_lens  = (const int*)d_in[1];
    const int*   out_lens = (const int*)d_in[2];
    int B = in_sizes[1];
    if (B > MAXB) B = MAXB;

    const int rows = B * TQ;
    const int warps_per_block = 8;
    lse_kernel<<<(rows + warps_per_block - 1) / warps_per_block,
                 warps_per_block * 32>>>(attn, in_lens, out_lens, B);
    ctc_kernel<<<B, 832>>>(attn, in_lens, out_lens);
    reduce_kernel<<<1, 32>>>((float*)d_out, B);
}